// round 13
// baseline (speedup 1.0000x reference)
#include <cuda_runtime.h>
#include <cuda_bf16.h>
#include <cuda_fp16.h>
#include <math.h>
#include <stdint.h>

// ---------------------------------------------------------------------------
// Problem constants
// ---------------------------------------------------------------------------
#define BB   4
#define NN   256
#define OBS  64
#define QDIM 32
#define HH   256
#define DD   128
#define NOPS 8
#define QE   64
#define BN   (BB*NN)          // 1024 rows

#define EDGE_OFF 0
#define OP_OFF   (BB*NN*NN)                 // 262144
#define NEXT_OFF (OP_OFF + BB*NN*NN*NOPS)   // 2359296

// ---------------------------------------------------------------------------
// Device scratch
// ---------------------------------------------------------------------------
__device__ float g_lat[BN*DD];
__device__ __half g_ELh[BN*HH];
__device__ __half g_ERh[BN*HH];
__device__ __half g_OLh[BN*HH];
__device__ __half g_ORh[BN*HH];
// fp16 pair-head weights: [s(4)][n(128)][k(128)], s = head*2 + half
__device__ __half g_Bfp[4*128*128];
// fp16 op layer-2 weights: [half(2)][n(8)][k(128)]
__device__ __half g_w2of[2*8*128];

__device__ __forceinline__ float sigf(float x){ return 1.0f/(1.0f+expf(-x)); }

__device__ __forceinline__ uint32_t smem_u32(const void* p){
    uint32_t a;
    asm("{ .reg .u64 t; cvta.to.shared.u64 t, %1; cvt.u32.u64 %0, t; }"
        : "=r"(a) : "l"(p));
    return a;
}

__device__ __forceinline__ void ldsm4(uint32_t& r0, uint32_t& r1, uint32_t& r2,
                                      uint32_t& r3, uint32_t addr){
    asm volatile("ldmatrix.sync.aligned.m8n8.x4.shared.b16 {%0,%1,%2,%3}, [%4];"
                 : "=r"(r0), "=r"(r1), "=r"(r2), "=r"(r3) : "r"(addr));
}
__device__ __forceinline__ void ldsm2(uint32_t& r0, uint32_t& r1, uint32_t addr){
    asm volatile("ldmatrix.sync.aligned.m8n8.x2.shared.b16 {%0,%1}, [%2];"
                 : "=r"(r0), "=r"(r1) : "r"(addr));
}
__device__ __forceinline__ void mma16816(float* d, uint32_t a0, uint32_t a1,
                                         uint32_t a2, uint32_t a3,
                                         uint32_t b0, uint32_t b1){
    asm volatile(
        "mma.sync.aligned.m16n8k16.row.col.f32.f16.f16.f32 "
        "{%0,%1,%2,%3}, {%4,%5,%6,%7}, {%8,%9}, {%0,%1,%2,%3};"
        : "+f"(d[0]), "+f"(d[1]), "+f"(d[2]), "+f"(d[3])
        : "r"(a0), "r"(a1), "r"(a2), "r"(a3), "r"(b0), "r"(b1));
}
__device__ __forceinline__ uint32_t packh2(float a, float b){
    __half2 h = __floats2half2_rn(a, b);
    return *reinterpret_cast<uint32_t*>(&h);
}

// ---------------------------------------------------------------------------
// Kernel A: per-node pipeline with smem-staged weight tiles.
// 4 rows/block x 256 blocks + 64 prep blocks (fp16 weight conversion).
// ---------------------------------------------------------------------------
#define STAGE(src, nf4) \
    for (int i_ = t; i_ < (nf4); i_ += 256) \
        ((float4*)s_w)[i_] = ((const float4*)(src))[i_];

__global__ __launch_bounds__(256)
void nodeKernel(const float* __restrict__ obs, const float* __restrict__ latent,
                const float* __restrict__ query,
                const float* __restrict__ enc_w1, const float* __restrict__ enc_b1,
                const float* __restrict__ enc_w2, const float* __restrict__ enc_b2,
                const float* __restrict__ upd_w,  const float* __restrict__ upd_b,
                const float* __restrict__ gru_wi, const float* __restrict__ gru_bi,
                const float* __restrict__ gru_wh, const float* __restrict__ gru_bh,
                const float* __restrict__ q_w,    const float* __restrict__ q_b,
                const float* __restrict__ nh_w1,  const float* __restrict__ nh_b1,
                const float* __restrict__ nh_w2,  const float* __restrict__ nh_b2,
                const float* __restrict__ eh_w1,  const float* __restrict__ oh_w1,
                const float* __restrict__ oh_w2,
                float* __restrict__ out_next)
{
    const int t = threadIdx.x;

    if (blockIdx.x >= 256){
        // ---- merged prepB: fp16 conversion of pair-head weights ----
        int bx = blockIdx.x - 256;
        int gi0 = bx * 1024 + t;
        #pragma unroll
        for (int i = 0; i < 4; i++){
            int gi = gi0 + i*256;            // 0..65535 over (s,n,k)
            int s   = gi >> 14;
            int rem = gi & 16383;
            int n   = rem >> 7;
            int k   = rem & 127;
            int head = s >> 1, half = s & 1;
            const float* w = head ? oh_w1 : eh_w1;
            g_Bfp[(s*128 + n)*128 + k] = __float2half(w[(256 + k)*256 + half*128 + n]);
        }
        if (bx == 0){
            for (int idx = t; idx < 2048; idx += 256){
                int half = idx >> 10, rem = idx & 1023;
                int n = rem >> 7, k = rem & 127;
                g_w2of[idx] = __float2half(oh_w2[(half*128 + k)*8 + n]);
            }
        }
        return;
    }

    __shared__ float s_w  [16*384];   // weight staging (24 KB)
    __shared__ float s_obs[4*64];     // later q_emb [4][64]
    __shared__ float s_h1 [4*256];    // later: [0:512)=upd, [512:1024)=lat
    __shared__ float s_emb[4*256];
    __shared__ float s_gi [4*384];    // later query tmp [4][32]
    __shared__ float s_gh [4*384];    // later nh hidden [4][256]

    const int row0 = blockIdx.x * 4;

    s_obs[t] = obs[row0*64 + t];

    // ---- h1 = relu(obs @ enc_w1 + b1) ----
    {
        float acc[4];
        float bv = enc_b1[t];
        #pragma unroll
        for (int r=0;r<4;r++) acc[r] = bv;
        for (int k0 = 0; k0 < 64; k0 += 16){
            __syncthreads();
            STAGE(enc_w1 + k0*256, 1024);
            __syncthreads();
            #pragma unroll
            for (int kk = 0; kk < 16; kk++){
                float w = s_w[kk*256 + t];
                #pragma unroll
                for (int r=0;r<4;r++) acc[r] = fmaf(s_obs[r*64 + k0 + kk], w, acc[r]);
            }
        }
        #pragma unroll
        for (int r=0;r<4;r++) s_h1[r*256+t] = fmaxf(acc[r], 0.0f);
    }

    // ---- node_emb = relu(h1 @ enc_w2 + b2) ----
    {
        float acc[4];
        float bv = enc_b2[t];
        #pragma unroll
        for (int r=0;r<4;r++) acc[r] = bv;
        for (int k0 = 0; k0 < 256; k0 += 16){
            __syncthreads();
            STAGE(enc_w2 + k0*256, 1024);
            __syncthreads();
            #pragma unroll
            for (int kk = 0; kk < 16; kk++){
                float w = s_w[kk*256 + t];
                #pragma unroll
                for (int r=0;r<4;r++) acc[r] = fmaf(s_h1[r*256 + k0 + kk], w, acc[r]);
            }
        }
        #pragma unroll
        for (int r=0;r<4;r++) s_emb[r*256+t] = fmaxf(acc[r], 0.0f);
    }

    float* s_upd = s_h1;          // [4][128]
    float* s_lat = s_h1 + 512;    // [4][128]

    // ---- upd = node_emb @ upd_w + b ----
    {
        const int o = t & 127;
        const int rbase = (t >> 7) * 2;
        float acc[2];
        float bv = upd_b[o];
        acc[0] = bv; acc[1] = bv;
        for (int k0 = 0; k0 < 256; k0 += 16){
            __syncthreads();
            STAGE(upd_w + k0*128, 512);
            __syncthreads();
            #pragma unroll
            for (int kk = 0; kk < 16; kk++){
                float w = s_w[kk*128 + o];
                acc[0] = fmaf(s_emb[rbase*256 + k0 + kk], w, acc[0]);
                acc[1] = fmaf(s_emb[(rbase+1)*256 + k0 + kk], w, acc[1]);
            }
        }
        s_upd[rbase*128 + o]     = acc[0];
        s_upd[(rbase+1)*128 + o] = acc[1];
    }
    for (int idx = t; idx < 512; idx += 256) s_lat[idx] = latent[row0*128 + idx];

    // ---- gi = upd @ gru_wi + bi ----
    {
        float a0[4], a1[4];
        float b0 = gru_bi[t];
        float b1 = (t < 128) ? gru_bi[256 + t] : 0.0f;
        #pragma unroll
        for (int r=0;r<4;r++){ a0[r] = b0; a1[r] = b1; }
        for (int k0 = 0; k0 < 128; k0 += 16){
            __syncthreads();
            STAGE(gru_wi + k0*384, 1536);
            __syncthreads();
            #pragma unroll
            for (int kk = 0; kk < 16; kk++){
                float w0 = s_w[kk*384 + t];
                #pragma unroll
                for (int r=0;r<4;r++) a0[r] = fmaf(s_upd[r*128 + k0 + kk], w0, a0[r]);
                if (t < 128){
                    float w1 = s_w[kk*384 + 256 + t];
                    #pragma unroll
                    for (int r=0;r<4;r++) a1[r] = fmaf(s_upd[r*128 + k0 + kk], w1, a1[r]);
                }
            }
        }
        #pragma unroll
        for (int r=0;r<4;r++) s_gi[r*384 + t] = a0[r];
        if (t < 128){
            #pragma unroll
            for (int r=0;r<4;r++) s_gi[r*384 + 256 + t] = a1[r];
        }
    }

    // ---- gh = latent @ gru_wh + bh ----
    {
        float a0[4], a1[4];
        float b0 = gru_bh[t];
        float b1 = (t < 128) ? gru_bh[256 + t] : 0.0f;
        #pragma unroll
        for (int r=0;r<4;r++){ a0[r] = b0; a1[r] = b1; }
        for (int k0 = 0; k0 < 128; k0 += 16){
            __syncthreads();
            STAGE(gru_wh + k0*384, 1536);
            __syncthreads();
            #pragma unroll
            for (int kk = 0; kk < 16; kk++){
                float w0 = s_w[kk*384 + t];
                #pragma unroll
                for (int r=0;r<4;r++) a0[r] = fmaf(s_lat[r*128 + k0 + kk], w0, a0[r]);
                if (t < 128){
                    float w1 = s_w[kk*384 + 256 + t];
                    #pragma unroll
                    for (int r=0;r<4;r++) a1[r] = fmaf(s_lat[r*128 + k0 + kk], w1, a1[r]);
                }
            }
        }
        #pragma unroll
        for (int r=0;r<4;r++) s_gh[r*384 + t] = a0[r];
        if (t < 128){
            #pragma unroll
            for (int r=0;r<4;r++) s_gh[r*384 + 256 + t] = a1[r];
        }
    }
    __syncthreads();

    // ---- GRU elementwise ----
    for (int idx = t; idx < 512; idx += 256){
        int r = idx >> 7, d = idx & 127;
        float ir = s_gi[r*384 + d],  iz = s_gi[r*384 + 128 + d], inn = s_gi[r*384 + 256 + d];
        float hr = s_gh[r*384 + d],  hz = s_gh[r*384 + 128 + d], hn  = s_gh[r*384 + 256 + d];
        float rg = sigf(ir + hr);
        float zg = sigf(iz + hz);
        float nh = tanhf(inn + rg*hn);
        float lv = (1.0f - zg)*nh + zg*s_lat[idx];
        s_lat[idx] = lv;
        g_lat[row0*128 + idx] = lv;
    }
    __syncthreads();

    // ---- q_emb = relu(query @ q_w + b) ----
    if (t < 128) s_gi[t] = query[row0*32 + t];
    __syncthreads();
    {
        int r = t >> 6, o = t & 63;
        float acc = q_b[o];
        #pragma unroll
        for (int k=0;k<32;k++) acc = fmaf(s_gi[r*32+k], q_w[k*64+o], acc);
        s_obs[t] = fmaxf(acc, 0.0f);
    }

    // ---- nh hidden = relu([lat, emb, q] @ nh_w1 + b) ----
    {
        float acc[4];
        float bv = nh_b1[t];
        #pragma unroll
        for (int r=0;r<4;r++) acc[r] = bv;
        for (int k0 = 0; k0 < 128; k0 += 16){
            __syncthreads();
            STAGE(nh_w1 + k0*256, 1024);
            __syncthreads();
            #pragma unroll
            for (int kk = 0; kk < 16; kk++){
                float w = s_w[kk*256 + t];
                #pragma unroll
                for (int r=0;r<4;r++) acc[r] = fmaf(s_lat[r*128 + k0 + kk], w, acc[r]);
            }
        }
        for (int k0 = 0; k0 < 256; k0 += 16){
            __syncthreads();
            STAGE(nh_w1 + (128 + k0)*256, 1024);
            __syncthreads();
            #pragma unroll
            for (int kk = 0; kk < 16; kk++){
                float w = s_w[kk*256 + t];
                #pragma unroll
                for (int r=0;r<4;r++) acc[r] = fmaf(s_emb[r*256 + k0 + kk], w, acc[r]);
            }
        }
        for (int k0 = 0; k0 < 64; k0 += 16){
            __syncthreads();
            STAGE(nh_w1 + (384 + k0)*256, 1024);
            __syncthreads();
            #pragma unroll
            for (int kk = 0; kk < 16; kk++){
                float w = s_w[kk*256 + t];
                #pragma unroll
                for (int r=0;r<4;r++) acc[r] = fmaf(s_obs[r*64 + k0 + kk], w, acc[r]);
            }
        }
        #pragma unroll
        for (int r=0;r<4;r++) s_gh[r*256+t] = fmaxf(acc[r], 0.0f);
    }
    __syncthreads();

    // ---- next_pred ----
    {
        const int w = t >> 5, l = t & 31;
        if (w < 4){
            float p = 0.0f;
            for (int o = l; o < 256; o += 32) p = fmaf(s_gh[w*256 + o], nh_w2[o], p);
            #pragma unroll
            for (int off = 16; off; off >>= 1) p += __shfl_down_sync(0xffffffffu, p, off);
            if (l == 0) out_next[row0 + w] = p + nh_b2[0];
        }
    }
}

// ---------------------------------------------------------------------------
// Kernel B: EL/ER/OL/OR = lat @ W_slice (+bias), fp16, staged weights.
// ---------------------------------------------------------------------------
__global__ __launch_bounds__(256)
void elKernel(const float* __restrict__ eh_w1, const float* __restrict__ eh_b1,
              const float* __restrict__ oh_w1, const float* __restrict__ oh_b1)
{
    __shared__ float s_lat[8*128];
    __shared__ float s_w[16*256];
    const int t = threadIdx.x;
    const int row0 = blockIdx.x * 8;
    const int m = blockIdx.y;

    const float* W; const float* bias = nullptr; __half* dst;
    if (m == 0)      { W = eh_w1;            bias = eh_b1; dst = g_ELh; }
    else if (m == 1) { W = eh_w1 + 128*256;                dst = g_ERh; }
    else if (m == 2) { W = oh_w1;            bias = oh_b1; dst = g_OLh; }
    else             { W = oh_w1 + 128*256;                dst = g_ORh; }

    for (int idx = t; idx < 1024; idx += 256) s_lat[idx] = g_lat[row0*128 + idx];

    float acc[8];
    float bv = bias ? bias[t] : 0.0f;
    #pragma unroll
    for (int r=0;r<8;r++) acc[r] = bv;
    for (int k0 = 0; k0 < 128; k0 += 16){
        __syncthreads();
        STAGE(W + k0*256, 1024);
        __syncthreads();
        #pragma unroll
        for (int kk = 0; kk < 16; kk++){
            float w = s_w[kk*256 + t];
            #pragma unroll
            for (int r=0;r<8;r++) acc[r] = fmaf(s_lat[r*128 + k0 + kk], w, acc[r]);
        }
    }
    #pragma unroll
    for (int r=0;r<8;r++) dst[(row0+r)*256 + t] = __float2half(acc[r]);
}

// ---------------------------------------------------------------------------
// Kernel C: pair MLP. CTA tile 8i x 32j = 256 pairs, 256 threads, 8 warps.
// TWO CTAs per SM (smem 112.4KB, regs capped at 128). Unchanged from R10.
// ---------------------------------------------------------------------------
#define OFF_A    0                         // 256 rows * 256B = 65536
#define OFF_B    65536                     // 128 rows * 256B = 32768
#define OFF_ELI  98304                     // 8*136*2  = 2176
#define OFF_ERJ  100480                    // 32*136*2 = 8704
#define OFF_W2E  109184                    // 256*4 = 1024
#define OFF_W2O  110208                    // 8 rows * 272B = 2176
#define PAIR_SMEM 112384

__global__ __launch_bounds__(256, 2)
void pairKernel(const float* __restrict__ eh_w2, const float* __restrict__ eh_b2,
                const float* __restrict__ oh_b2,
                float* __restrict__ out)
{
    extern __shared__ __align__(16) char sm[];
    float*  s_li   = (float*)(sm + OFF_B);          // prologue staging [8][128]
    float*  s_lj   = (float*)(sm + OFF_B + 4096);   // prologue staging [32][128]
    __half* s_eli  = (__half*)(sm + OFF_ELI);       // per-stage [8][136]
    __half* s_erj  = (__half*)(sm + OFF_ERJ);       // per-stage [32][136]
    float*  s_w2e  = (float*)(sm + OFF_W2E);        // [256] (both halves)

    const uint32_t smb = smem_u32(sm);
    const int t    = threadIdx.x;
    const int wid  = t >> 5;
    const int lane = t & 31;
    const int b    = blockIdx.z;
    const int i0   = blockIdx.y * 8;
    const int j0   = blockIdx.x * 32;
    const int base = b * NN;

    // ---- prologue: stage lat rows (into B region) + w2e ----
    for (int idx = t; idx < 1024; idx += 256) s_li[idx] = g_lat[(base + i0)*128 + idx];
    for (int idx = t; idx < 4096; idx += 256) s_lj[idx] = g_lat[(base + j0)*128 + idx];
    if (t < 256) s_w2e[t] = eh_w2[t];
    __syncthreads();

    // ---- build A = |li - lj| fp16, 256 rows x 256B, XOR swizzle ----
    for (int c = t; c < 4096; c += 256){
        int p = c >> 4, kg = c & 15;          // p: pair row, kg: 16B chunk
        int il = p >> 5, jl = p & 31;
        const float4* li4 = (const float4*)&s_li[il*128 + kg*8];
        const float4* lj4 = (const float4*)&s_lj[jl*128 + kg*8];
        float4 x0 = li4[0], x1 = li4[1], y0 = lj4[0], y1 = lj4[1];
        float a[8] = { fabsf(x0.x-y0.x), fabsf(x0.y-y0.y), fabsf(x0.z-y0.z), fabsf(x0.w-y0.w),
                       fabsf(x1.x-y1.x), fabsf(x1.y-y1.y), fabsf(x1.z-y1.z), fabsf(x1.w-y1.w) };
        uint32_t hp[4];
        #pragma unroll
        for (int q = 0; q < 4; q++) hp[q] = packh2(a[2*q], a[2*q+1]);
        uint32_t boff = (uint32_t)(p*256 + ((kg ^ (p & 7)) << 4));
        *(uint4*)(sm + OFF_A + boff) = make_uint4(hp[0],hp[1],hp[2],hp[3]);
    }

    // ldmatrix geometry
    const uint32_t sw    = (uint32_t)(lane & 7);
    const uint32_t aBase0 = smb + OFF_A
        + (uint32_t)(wid*32 + (lane & 7) + ((lane >> 3) & 1)*8) * 256;
    const uint32_t aBase1 = aBase0 + 16*256;
    const uint32_t kbitA = (uint32_t)((lane >> 4) & 1);
    const uint32_t bBase = smb + OFF_B
        + (uint32_t)((lane & 7) + ((lane >> 4) & 1)*8) * 256;
    const uint32_t kbitB = (uint32_t)((lane >> 3) & 1);
    const uint32_t wbBase = smb + OFF_W2O + (uint32_t)(lane & 7)*272
        + (uint32_t)((lane >> 3) & 1)*16;

    // epilogue geometry: thread owns rows r0,r0+8 (mb0), r0+16,r0+24 (mb1)
    const int r0  = lane >> 2;
    const int cq  = 2*(lane & 3);
    const int ig  = i0 + wid;

    float eacc[4] = {0.0f, 0.0f, 0.0f, 0.0f};
    float opA[4] = {0.0f, 0.0f, 0.0f, 0.0f};
    float opB[4] = {0.0f, 0.0f, 0.0f, 0.0f};

    for (int s = 0; s < 4; s++){
        const int head = s >> 1, half = s & 1;
        __syncthreads();     // A-build done (s=0) / prev stage epilogue done

        // stage B fp16 (swizzled)
        const __half* srcB = &g_Bfp[(size_t)s*16384];
        for (int idx = t; idx < 2048; idx += 256){
            int n = idx >> 4, kg = idx & 15;
            uint4 v = *(const uint4*)(srcB + n*128 + kg*8);
            *(uint4*)(sm + OFF_B + n*256 + ((kg ^ (n & 7)) << 4)) = v;
        }
        // stage EL (8 rows) / ER (32 rows), fp16, 16B chunks
        const __half* gl = head ? g_OLh : g_ELh;
        const __half* gr = head ? g_ORh : g_ERh;
        for (int idx = t; idx < 128; idx += 256){
            int r = idx >> 4, kg = idx & 15;
            uint4 v = *(const uint4*)(gl + (base + i0 + r)*256 + half*128 + kg*8);
            *(uint4*)(sm + OFF_ELI + r*272 + kg*16) = v;
        }
        for (int idx = t; idx < 512; idx += 256){
            int r = idx >> 4, kg = idx & 15;
            uint4 v = *(const uint4*)(gr + (base + j0 + r)*256 + half*128 + kg*8);
            *(uint4*)(sm + OFF_ERJ + r*272 + kg*16) = v;
        }
        // stage w2o fp16 for this half (op head only): [8][128] -> 272B rows
        if (head == 1){
            for (int idx = t; idx < 512; idx += 256){
                int n = idx >> 6, kp = idx & 63;
                uint32_t v = *(const uint32_t*)&g_w2of[half*1024 + n*128 + kp*2];
                *(uint32_t*)(sm + OFF_W2O + n*272 + kp*4) = v;
            }
        }
        __syncthreads();

        #pragma unroll
        for (int chunk = 0; chunk < 2; chunk++){
            float acc0[8][4], acc1[8][4];
            #pragma unroll
            for (int nt=0;nt<8;nt++)
                #pragma unroll
                for (int v=0;v<4;v++){ acc0[nt][v] = 0.0f; acc1[nt][v] = 0.0f; }

            #pragma unroll
            for (int ks = 0; ks < 8; ks++){
                const uint32_t aoff = ((((uint32_t)(2*ks) + kbitA) ^ sw) << 4);
                uint32_t p0,p1,p2,p3, q0,q1,q2,q3;
                ldsm4(p0,p1,p2,p3, aBase0 + aoff);
                ldsm4(q0,q1,q2,q3, aBase1 + aoff);
                const uint32_t bch = ((((uint32_t)(2*ks) + kbitB) ^ sw) << 4);
                #pragma unroll
                for (int ntp = 0; ntp < 4; ntp++){
                    uint32_t baddr = bBase + (uint32_t)(chunk*64 + ntp*16)*256 + bch;
                    uint32_t b0,b1,b2,b3;
                    ldsm4(b0,b1,b2,b3, baddr);
                    mma16816(acc0[2*ntp],   p0,p1,p2,p3, b0,b1);
                    mma16816(acc0[2*ntp+1], p0,p1,p2,p3, b2,b3);
                    mma16816(acc1[2*ntp],   q0,q1,q2,q3, b0,b1);
                    mma16816(acc1[2*ntp+1], q0,q1,q2,q3, b2,b3);
                }
            }

            // ---- epilogue for this 64-col chunk (fp16 tables, f32 math) ----
            #pragma unroll
            for (int qf = 0; qf < 4; qf++){
                uint32_t fa[4], fb[4];
                #pragma unroll
                for (int e = 0; e < 2; e++){
                    const int nt = qf*2 + e;
                    const int c0 = chunk*64 + nt*8 + cq;
                    float2 el = __half22float2(*(const __half2*)&s_eli[wid*136 + c0]);
                    float2 e0 = __half22float2(*(const __half2*)&s_erj[r0*136 + c0]);
                    float2 e1 = __half22float2(*(const __half2*)&s_erj[(r0+8)*136 + c0]);
                    float2 e2 = __half22float2(*(const __half2*)&s_erj[(r0+16)*136 + c0]);
                    float2 e3 = __half22float2(*(const __half2*)&s_erj[(r0+24)*136 + c0]);
                    float h00 = fmaxf(acc0[nt][0] + el.x + e0.x, 0.0f);
                    float h01 = fmaxf(acc0[nt][1] + el.y + e0.y, 0.0f);
                    float h10 = fmaxf(acc0[nt][2] + el.x + e1.x, 0.0f);
                    float h11 = fmaxf(acc0[nt][3] + el.y + e1.y, 0.0f);
                    float h20 = fmaxf(acc1[nt][0] + el.x + e2.x, 0.0f);
                    float h21 = fmaxf(acc1[nt][1] + el.y + e2.y, 0.0f);
                    float h30 = fmaxf(acc1[nt][2] + el.x + e3.x, 0.0f);
                    float h31 = fmaxf(acc1[nt][3] + el.y + e3.y, 0.0f);
                    if (head == 0){
                        const float2 w2 = *(const float2*)&s_w2e[half*128 + c0];
                        eacc[0] = fmaf(h00, w2.x, fmaf(h01, w2.y, eacc[0]));
                        eacc[1] = fmaf(h10, w2.x, fmaf(h11, w2.y, eacc[1]));
                        eacc[2] = fmaf(h20, w2.x, fmaf(h21, w2.y, eacc[2]));
                        eacc[3] = fmaf(h30, w2.x, fmaf(h31, w2.y, eacc[3]));
                    } else {
                        fa[e*2]   = packh2(h00, h01);
                        fa[e*2+1] = packh2(h10, h11);
                        fb[e*2]   = packh2(h20, h21);
                        fb[e*2+1] = packh2(h30, h31);
                    }
                }
                if (head == 1){
                    uint32_t wb0, wb1;
                    ldsm2(wb0, wb1, wbBase + (uint32_t)(chunk*128 + qf*32));
                    mma16816(opA, fa[0],fa[1],fa[2],fa[3], wb0, wb1);
                    mma16816(opB, fb[0],fb[1],fb[2],fb[3], wb0, wb1);
                }
            }
        }

        if (s == 1){
            #pragma unroll
            for (int rh = 0; rh < 4; rh++){
                float v = eacc[rh];
                v += __shfl_xor_sync(0xffffffffu, v, 1);
                v += __shfl_xor_sync(0xffffffffu, v, 2);
                eacc[rh] = v;
            }
            if ((lane & 3) == 0){
                float b2 = eh_b2[0];
                #pragma unroll
                for (int rh = 0; rh < 4; rh++){
                    int jg = j0 + r0 + rh*8;
                    float v = eacc[rh] + b2;
                    if (ig == jg) v = -8.0f;
                    out[EDGE_OFF + b*NN*NN + ig*NN + jg] = v;
                }
            }
        }
    }

    // ---- op output: C layout rows r0,r0+8 (opA), r0+16,r0+24 (opB) ----
    {
        const float bo0 = oh_b2[cq], bo1 = oh_b2[cq + 1];
        #pragma unroll
        for (int mb = 0; mb < 2; mb++){
            const float* oc = mb ? opB : opA;
            #pragma unroll
            for (int rr = 0; rr < 2; rr++){
                int jg = j0 + r0 + mb*16 + rr*8;
                float2* dst = (float2*)&out[OP_OFF
                    + ((size_t)(b*NN*NN + ig*NN + jg))*NOPS + cq];
                *dst = make_float2(oc[rr*2] + bo0, oc[rr*2+1] + bo1);
            }
        }
    }
}

// ---------------------------------------------------------------------------
// Launch
// ---------------------------------------------------------------------------
extern "C" void kernel_launch(void* const* d_in, const int* in_sizes, int n_in,
                              void* d_out, int out_size)
{
    const float* obs    = (const float*)d_in[0];
    const float* latent = (const float*)d_in[1];
    const float* query  = (const float*)d_in[2];
    const float* enc_w1 = (const float*)d_in[3];
    const float* enc_b1 = (const float*)d_in[4];
    const float* enc_w2 = (const float*)d_in[5];
    const float* enc_b2 = (const float*)d_in[6];
    const float* upd_w  = (const float*)d_in[7];
    const float* upd_b  = (const float*)d_in[8];
    const float* gru_wi = (const float*)d_in[9];
    const float* gru_bi = (const float*)d_in[10];
    const float* gru_wh = (const float*)d_in[11];
    const float* gru_bh = (const float*)d_in[12];
    const float* eh_w1  = (const float*)d_in[13];
    const float* eh_b1  = (const float*)d_in[14];
    const float* eh_w2  = (const float*)d_in[15];
    const float* eh_b2  = (const float*)d_in[16];
    const float* oh_w1  = (const float*)d_in[17];
    const float* oh_b1  = (const float*)d_in[18];
    const float* oh_w2  = (const float*)d_in[19];
    const float* oh_b2  = (const float*)d_in[20];
    const float* q_w    = (const float*)d_in[21];
    const float* q_b    = (const float*)d_in[22];
    const float* nh_w1  = (const float*)d_in[23];
    const float* nh_b1  = (const float*)d_in[24];
    const float* nh_w2  = (const float*)d_in[25];
    const float* nh_b2  = (const float*)d_in[26];

    float* out = (float*)d_out;

    static bool inited = false;
    if (!inited){
        cudaFuncSetAttribute(pairKernel, cudaFuncAttributeMaxDynamicSharedMemorySize, PAIR_SMEM);
        inited = true;
    }

    nodeKernel<<<320, 256>>>(obs, latent, query,
                             enc_w1, enc_b1, enc_w2, enc_b2,
                             upd_w, upd_b,
                             gru_wi, gru_bi, gru_wh, gru_bh,
                             q_w, q_b, nh_w1, nh_b1, nh_w2, nh_b2,
                             eh_w1, oh_w1, oh_w2,
                             out + NEXT_OFF);

    elKernel<<<dim3(128, 4), 256>>>(eh_w1, eh_b1, oh_w1, oh_b1);

    pairKernel<<<dim3(8, 32, 4), 256, PAIR_SMEM>>>(eh_w2, eh_b2, oh_b2, out);
}

// round 14
// speedup vs baseline: 1.2386x; 1.2386x over previous
#include <cuda_runtime.h>
#include <cuda_bf16.h>
#include <cuda_fp16.h>
#include <math.h>
#include <stdint.h>

// ---------------------------------------------------------------------------
// Problem constants
// ---------------------------------------------------------------------------
#define BB   4
#define NN   256
#define OBS  64
#define QDIM 32
#define HH   256
#define DD   128
#define NOPS 8
#define QE   64
#define BN   (BB*NN)          // 1024 rows

#define EDGE_OFF 0
#define OP_OFF   (BB*NN*NN)                 // 262144
#define NEXT_OFF (OP_OFF + BB*NN*NN*NOPS)   // 2359296

// ---------------------------------------------------------------------------
// Device scratch
// ---------------------------------------------------------------------------
__device__ float g_lat[BN*DD];
__device__ __half g_ELh[BN*HH];
__device__ __half g_ERh[BN*HH];
__device__ __half g_OLh[BN*HH];
__device__ __half g_ORh[BN*HH];
// fp16 pair-head weights: [s(4)][n(128)][k(128)], s = head*2 + half
__device__ __half g_Bfp[4*128*128];
// fp16 op layer-2 weights: [half(2)][n(8)][k(128)]
__device__ __half g_w2of[2*8*128];

__device__ __forceinline__ float sigf(float x){ return 1.0f/(1.0f+expf(-x)); }

__device__ __forceinline__ uint32_t smem_u32(const void* p){
    uint32_t a;
    asm("{ .reg .u64 t; cvta.to.shared.u64 t, %1; cvt.u32.u64 %0, t; }"
        : "=r"(a) : "l"(p));
    return a;
}

__device__ __forceinline__ void ldsm4(uint32_t& r0, uint32_t& r1, uint32_t& r2,
                                      uint32_t& r3, uint32_t addr){
    asm volatile("ldmatrix.sync.aligned.m8n8.x4.shared.b16 {%0,%1,%2,%3}, [%4];"
                 : "=r"(r0), "=r"(r1), "=r"(r2), "=r"(r3) : "r"(addr));
}
__device__ __forceinline__ void ldsm2(uint32_t& r0, uint32_t& r1, uint32_t addr){
    asm volatile("ldmatrix.sync.aligned.m8n8.x2.shared.b16 {%0,%1}, [%2];"
                 : "=r"(r0), "=r"(r1) : "r"(addr));
}
__device__ __forceinline__ void mma16816(float* d, uint32_t a0, uint32_t a1,
                                         uint32_t a2, uint32_t a3,
                                         uint32_t b0, uint32_t b1){
    asm volatile(
        "mma.sync.aligned.m16n8k16.row.col.f32.f16.f16.f32 "
        "{%0,%1,%2,%3}, {%4,%5,%6,%7}, {%8,%9}, {%0,%1,%2,%3};"
        : "+f"(d[0]), "+f"(d[1]), "+f"(d[2]), "+f"(d[3])
        : "r"(a0), "r"(a1), "r"(a2), "r"(a3), "r"(b0), "r"(b1));
}
__device__ __forceinline__ uint32_t packh2(float a, float b){
    __half2 h = __floats2half2_rn(a, b);
    return *reinterpret_cast<uint32_t*>(&h);
}

// ---------------------------------------------------------------------------
// Kernel A: per-node pipeline. 4 rows/block x 256 blocks + 64 prep blocks.
// Weight k-loops unrolled 16 (MLP ~16) to hide L2-hit latency.
// ---------------------------------------------------------------------------
__global__ __launch_bounds__(256)
void nodeKernel(const float* __restrict__ obs, const float* __restrict__ latent,
                const float* __restrict__ query,
                const float* __restrict__ enc_w1, const float* __restrict__ enc_b1,
                const float* __restrict__ enc_w2, const float* __restrict__ enc_b2,
                const float* __restrict__ upd_w,  const float* __restrict__ upd_b,
                const float* __restrict__ gru_wi, const float* __restrict__ gru_bi,
                const float* __restrict__ gru_wh, const float* __restrict__ gru_bh,
                const float* __restrict__ q_w,    const float* __restrict__ q_b,
                const float* __restrict__ nh_w1,  const float* __restrict__ nh_b1,
                const float* __restrict__ nh_w2,  const float* __restrict__ nh_b2,
                const float* __restrict__ eh_w1,  const float* __restrict__ oh_w1,
                const float* __restrict__ oh_w2,
                float* __restrict__ out_next)
{
    const int t = threadIdx.x;

    if (blockIdx.x >= 256){
        // ---- merged prepB: fp16 conversion of pair-head weights ----
        int bx = blockIdx.x - 256;
        int gi0 = bx * 1024 + t;
        #pragma unroll
        for (int i = 0; i < 4; i++){
            int gi = gi0 + i*256;            // 0..65535 over (s,n,k)
            int s   = gi >> 14;
            int rem = gi & 16383;
            int n   = rem >> 7;
            int k   = rem & 127;
            int head = s >> 1, half = s & 1;
            const float* w = head ? oh_w1 : eh_w1;
            g_Bfp[(s*128 + n)*128 + k] = __float2half(w[(256 + k)*256 + half*128 + n]);
        }
        if (bx == 0){
            for (int idx = t; idx < 2048; idx += 256){
                int half = idx >> 10, rem = idx & 1023;
                int n = rem >> 7, k = rem & 127;
                g_w2of[idx] = __float2half(oh_w2[(half*128 + k)*8 + n]);
            }
        }
        return;
    }

    __shared__ float s_obs[4*64];
    __shared__ float s_h1 [4*256];
    __shared__ float s_emb[4*256];
    __shared__ float s_gi [4*384];
    __shared__ float s_gh [4*384];

    const int row0 = blockIdx.x * 4;

    s_obs[t] = obs[row0*64 + t];
    __syncthreads();

    // h1 = relu(obs @ enc_w1 + b1)
    {
        float acc[4];
        float bv = enc_b1[t];
        #pragma unroll
        for (int r=0;r<4;r++) acc[r] = bv;
        #pragma unroll 16
        for (int k=0;k<64;k++){
            float w = enc_w1[k*256 + t];
            #pragma unroll
            for (int r=0;r<4;r++) acc[r] = fmaf(s_obs[r*64+k], w, acc[r]);
        }
        #pragma unroll
        for (int r=0;r<4;r++) s_h1[r*256+t] = fmaxf(acc[r], 0.0f);
    }
    __syncthreads();

    // node_emb = relu(h1 @ enc_w2 + b2)
    {
        float acc[4];
        float bv = enc_b2[t];
        #pragma unroll
        for (int r=0;r<4;r++) acc[r] = bv;
        #pragma unroll 16
        for (int k=0;k<256;k++){
            float w = enc_w2[k*256 + t];
            #pragma unroll
            for (int r=0;r<4;r++) acc[r] = fmaf(s_h1[r*256+k], w, acc[r]);
        }
        __syncthreads();
        #pragma unroll
        for (int r=0;r<4;r++) s_emb[r*256+t] = fmaxf(acc[r], 0.0f);
    }
    __syncthreads();

    float* s_upd = s_h1;
    float* s_lat = s_h1 + 512;

    // upd = node_emb @ upd_w + b
    {
        const int o = t & 127;
        const int rbase = (t >> 7) * 2;
        float acc[2];
        float bv = upd_b[o];
        acc[0] = bv; acc[1] = bv;
        #pragma unroll 16
        for (int k=0;k<256;k++){
            float w = upd_w[k*128 + o];
            acc[0] = fmaf(s_emb[rbase*256+k], w, acc[0]);
            acc[1] = fmaf(s_emb[(rbase+1)*256+k], w, acc[1]);
        }
        s_upd[rbase*128+o]     = acc[0];
        s_upd[(rbase+1)*128+o] = acc[1];
    }
    for (int idx = t; idx < 512; idx += 256) s_lat[idx] = latent[row0*128 + idx];
    __syncthreads();

    // gi / gh
    for (int o = t; o < 384; o += 256){
        float ai[4], ah[4];
        float bi = gru_bi[o], bh = gru_bh[o];
        #pragma unroll
        for (int r=0;r<4;r++){ ai[r] = bi; ah[r] = bh; }
        #pragma unroll 8
        for (int k=0;k<128;k++){
            float wi = gru_wi[k*384 + o];
            float wh = gru_wh[k*384 + o];
            #pragma unroll
            for (int r=0;r<4;r++){
                ai[r] = fmaf(s_upd[r*128+k], wi, ai[r]);
                ah[r] = fmaf(s_lat[r*128+k], wh, ah[r]);
            }
        }
        #pragma unroll
        for (int r=0;r<4;r++){ s_gi[r*384+o] = ai[r]; s_gh[r*384+o] = ah[r]; }
    }
    __syncthreads();

    // GRU elementwise
    for (int idx = t; idx < 512; idx += 256){
        int r = idx >> 7, d = idx & 127;
        float ir = s_gi[r*384 + d],  iz = s_gi[r*384 + 128 + d], inn = s_gi[r*384 + 256 + d];
        float hr = s_gh[r*384 + d],  hz = s_gh[r*384 + 128 + d], hn  = s_gh[r*384 + 256 + d];
        float rg = sigf(ir + hr);
        float zg = sigf(iz + hz);
        float nh = tanhf(inn + rg*hn);
        float lv = (1.0f - zg)*nh + zg*s_lat[idx];
        s_lat[idx] = lv;
        g_lat[row0*128 + idx] = lv;
    }
    __syncthreads();

    // q_emb = relu(query @ q_w + b)
    if (t < 128) s_gi[t] = query[row0*32 + t];
    __syncthreads();
    {
        int r = t >> 6, o = t & 63;
        float acc = q_b[o];
        #pragma unroll
        for (int k=0;k<32;k++) acc = fmaf(s_gi[r*32+k], q_w[k*64+o], acc);
        s_obs[t] = fmaxf(acc, 0.0f);
    }
    __syncthreads();

    // nh hidden = relu([lat, emb, q] @ nh_w1 + b)
    {
        float acc[4];
        float bv = nh_b1[t];
        #pragma unroll
        for (int r=0;r<4;r++) acc[r] = bv;
        #pragma unroll 16
        for (int k=0;k<128;k++){
            float w = nh_w1[k*256 + t];
            #pragma unroll
            for (int r=0;r<4;r++) acc[r] = fmaf(s_lat[r*128+k], w, acc[r]);
        }
        #pragma unroll 16
        for (int k=0;k<256;k++){
            float w = nh_w1[(128+k)*256 + t];
            #pragma unroll
            for (int r=0;r<4;r++) acc[r] = fmaf(s_emb[r*256+k], w, acc[r]);
        }
        #pragma unroll 16
        for (int k=0;k<64;k++){
            float w = nh_w1[(384+k)*256 + t];
            #pragma unroll
            for (int r=0;r<4;r++) acc[r] = fmaf(s_obs[r*64+k], w, acc[r]);
        }
        #pragma unroll
        for (int r=0;r<4;r++) s_gh[r*256+t] = fmaxf(acc[r], 0.0f);
    }
    __syncthreads();

    // next_pred
    {
        const int w = t >> 5, l = t & 31;
        if (w < 4){
            float p = 0.0f;
            for (int o = l; o < 256; o += 32) p = fmaf(s_gh[w*256 + o], nh_w2[o], p);
            #pragma unroll
            for (int off = 16; off; off >>= 1) p += __shfl_down_sync(0xffffffffu, p, off);
            if (l == 0) out_next[row0 + w] = p + nh_b2[0];
        }
    }
}

// ---------------------------------------------------------------------------
// Kernel B: EL/ER/OL/OR = lat @ W_slice (+bias), stored fp16. grid (128,4).
// ---------------------------------------------------------------------------
__global__ __launch_bounds__(256)
void elKernel(const float* __restrict__ eh_w1, const float* __restrict__ eh_b1,
              const float* __restrict__ oh_w1, const float* __restrict__ oh_b1)
{
    __shared__ float s_lat[8*128];
    const int t = threadIdx.x;
    const int row0 = blockIdx.x * 8;
    const int m = blockIdx.y;

    const float* W; const float* bias = nullptr; __half* dst;
    if (m == 0)      { W = eh_w1;            bias = eh_b1; dst = g_ELh; }
    else if (m == 1) { W = eh_w1 + 128*256;                dst = g_ERh; }
    else if (m == 2) { W = oh_w1;            bias = oh_b1; dst = g_OLh; }
    else             { W = oh_w1 + 128*256;                dst = g_ORh; }

    for (int idx = t; idx < 1024; idx += 256) s_lat[idx] = g_lat[row0*128 + idx];
    __syncthreads();

    float acc[8];
    float bv = bias ? bias[t] : 0.0f;
    #pragma unroll
    for (int r=0;r<8;r++) acc[r] = bv;
    #pragma unroll 16
    for (int k=0;k<128;k++){
        float w = W[k*256 + t];
        #pragma unroll
        for (int r=0;r<8;r++) acc[r] = fmaf(s_lat[r*128+k], w, acc[r]);
    }
    #pragma unroll
    for (int r=0;r<8;r++) dst[(row0+r)*256 + t] = __float2half(acc[r]);
}

// ---------------------------------------------------------------------------
// Kernel C: pair MLP. CTA tile 8i x 32j = 256 pairs, 256 threads, 8 warps.
// TWO CTAs per SM (smem 112.4KB, regs capped at 128). Unchanged from R10.
// ---------------------------------------------------------------------------
#define OFF_A    0                         // 256 rows * 256B = 65536
#define OFF_B    65536                     // 128 rows * 256B = 32768
#define OFF_ELI  98304                     // 8*136*2  = 2176
#define OFF_ERJ  100480                    // 32*136*2 = 8704
#define OFF_W2E  109184                    // 256*4 = 1024
#define OFF_W2O  110208                    // 8 rows * 272B = 2176
#define PAIR_SMEM 112384

__global__ __launch_bounds__(256, 2)
void pairKernel(const float* __restrict__ eh_w2, const float* __restrict__ eh_b2,
                const float* __restrict__ oh_b2,
                float* __restrict__ out)
{
    extern __shared__ __align__(16) char sm[];
    float*  s_li   = (float*)(sm + OFF_B);          // prologue staging [8][128]
    float*  s_lj   = (float*)(sm + OFF_B + 4096);   // prologue staging [32][128]
    __half* s_eli  = (__half*)(sm + OFF_ELI);       // per-stage [8][136]
    __half* s_erj  = (__half*)(sm + OFF_ERJ);       // per-stage [32][136]
    float*  s_w2e  = (float*)(sm + OFF_W2E);        // [256] (both halves)

    const uint32_t smb = smem_u32(sm);
    const int t    = threadIdx.x;
    const int wid  = t >> 5;
    const int lane = t & 31;
    const int b    = blockIdx.z;
    const int i0   = blockIdx.y * 8;
    const int j0   = blockIdx.x * 32;
    const int base = b * NN;

    // ---- prologue: stage lat rows (into B region) + w2e ----
    for (int idx = t; idx < 1024; idx += 256) s_li[idx] = g_lat[(base + i0)*128 + idx];
    for (int idx = t; idx < 4096; idx += 256) s_lj[idx] = g_lat[(base + j0)*128 + idx];
    if (t < 256) s_w2e[t] = eh_w2[t];
    __syncthreads();

    // ---- build A = |li - lj| fp16, 256 rows x 256B, XOR swizzle ----
    for (int c = t; c < 4096; c += 256){
        int p = c >> 4, kg = c & 15;          // p: pair row, kg: 16B chunk
        int il = p >> 5, jl = p & 31;
        const float4* li4 = (const float4*)&s_li[il*128 + kg*8];
        const float4* lj4 = (const float4*)&s_lj[jl*128 + kg*8];
        float4 x0 = li4[0], x1 = li4[1], y0 = lj4[0], y1 = lj4[1];
        float a[8] = { fabsf(x0.x-y0.x), fabsf(x0.y-y0.y), fabsf(x0.z-y0.z), fabsf(x0.w-y0.w),
                       fabsf(x1.x-y1.x), fabsf(x1.y-y1.y), fabsf(x1.z-y1.z), fabsf(x1.w-y1.w) };
        uint32_t hp[4];
        #pragma unroll
        for (int q = 0; q < 4; q++) hp[q] = packh2(a[2*q], a[2*q+1]);
        uint32_t boff = (uint32_t)(p*256 + ((kg ^ (p & 7)) << 4));
        *(uint4*)(sm + OFF_A + boff) = make_uint4(hp[0],hp[1],hp[2],hp[3]);
    }

    // ldmatrix geometry
    const uint32_t sw    = (uint32_t)(lane & 7);
    const uint32_t aBase0 = smb + OFF_A
        + (uint32_t)(wid*32 + (lane & 7) + ((lane >> 3) & 1)*8) * 256;
    const uint32_t aBase1 = aBase0 + 16*256;
    const uint32_t kbitA = (uint32_t)((lane >> 4) & 1);
    const uint32_t bBase = smb + OFF_B
        + (uint32_t)((lane & 7) + ((lane >> 4) & 1)*8) * 256;
    const uint32_t kbitB = (uint32_t)((lane >> 3) & 1);
    const uint32_t wbBase = smb + OFF_W2O + (uint32_t)(lane & 7)*272
        + (uint32_t)((lane >> 3) & 1)*16;

    // epilogue geometry: thread owns rows r0,r0+8 (mb0), r0+16,r0+24 (mb1)
    const int r0  = lane >> 2;
    const int cq  = 2*(lane & 3);
    const int ig  = i0 + wid;

    float eacc[4] = {0.0f, 0.0f, 0.0f, 0.0f};
    float opA[4] = {0.0f, 0.0f, 0.0f, 0.0f};
    float opB[4] = {0.0f, 0.0f, 0.0f, 0.0f};

    for (int s = 0; s < 4; s++){
        const int head = s >> 1, half = s & 1;
        __syncthreads();     // A-build done (s=0) / prev stage epilogue done

        // stage B fp16 (swizzled)
        const __half* srcB = &g_Bfp[(size_t)s*16384];
        for (int idx = t; idx < 2048; idx += 256){
            int n = idx >> 4, kg = idx & 15;
            uint4 v = *(const uint4*)(srcB + n*128 + kg*8);
            *(uint4*)(sm + OFF_B + n*256 + ((kg ^ (n & 7)) << 4)) = v;
        }
        // stage EL (8 rows) / ER (32 rows), fp16, 16B chunks
        const __half* gl = head ? g_OLh : g_ELh;
        const __half* gr = head ? g_ORh : g_ERh;
        for (int idx = t; idx < 128; idx += 256){
            int r = idx >> 4, kg = idx & 15;
            uint4 v = *(const uint4*)(gl + (base + i0 + r)*256 + half*128 + kg*8);
            *(uint4*)(sm + OFF_ELI + r*272 + kg*16) = v;
        }
        for (int idx = t; idx < 512; idx += 256){
            int r = idx >> 4, kg = idx & 15;
            uint4 v = *(const uint4*)(gr + (base + j0 + r)*256 + half*128 + kg*8);
            *(uint4*)(sm + OFF_ERJ + r*272 + kg*16) = v;
        }
        // stage w2o fp16 for this half (op head only): [8][128] -> 272B rows
        if (head == 1){
            for (int idx = t; idx < 512; idx += 256){
                int n = idx >> 6, kp = idx & 63;
                uint32_t v = *(const uint32_t*)&g_w2of[half*1024 + n*128 + kp*2];
                *(uint32_t*)(sm + OFF_W2O + n*272 + kp*4) = v;
            }
        }
        __syncthreads();

        #pragma unroll
        for (int chunk = 0; chunk < 2; chunk++){
            float acc0[8][4], acc1[8][4];
            #pragma unroll
            for (int nt=0;nt<8;nt++)
                #pragma unroll
                for (int v=0;v<4;v++){ acc0[nt][v] = 0.0f; acc1[nt][v] = 0.0f; }

            #pragma unroll
            for (int ks = 0; ks < 8; ks++){
                const uint32_t aoff = ((((uint32_t)(2*ks) + kbitA) ^ sw) << 4);
                uint32_t p0,p1,p2,p3, q0,q1,q2,q3;
                ldsm4(p0,p1,p2,p3, aBase0 + aoff);
                ldsm4(q0,q1,q2,q3, aBase1 + aoff);
                const uint32_t bch = ((((uint32_t)(2*ks) + kbitB) ^ sw) << 4);
                #pragma unroll
                for (int ntp = 0; ntp < 4; ntp++){
                    uint32_t baddr = bBase + (uint32_t)(chunk*64 + ntp*16)*256 + bch;
                    uint32_t b0,b1,b2,b3;
                    ldsm4(b0,b1,b2,b3, baddr);
                    mma16816(acc0[2*ntp],   p0,p1,p2,p3, b0,b1);
                    mma16816(acc0[2*ntp+1], p0,p1,p2,p3, b2,b3);
                    mma16816(acc1[2*ntp],   q0,q1,q2,q3, b0,b1);
                    mma16816(acc1[2*ntp+1], q0,q1,q2,q3, b2,b3);
                }
            }

            // ---- epilogue for this 64-col chunk (fp16 tables, f32 math) ----
            #pragma unroll
            for (int qf = 0; qf < 4; qf++){
                uint32_t fa[4], fb[4];
                #pragma unroll
                for (int e = 0; e < 2; e++){
                    const int nt = qf*2 + e;
                    const int c0 = chunk*64 + nt*8 + cq;
                    float2 el = __half22float2(*(const __half2*)&s_eli[wid*136 + c0]);
                    float2 e0 = __half22float2(*(const __half2*)&s_erj[r0*136 + c0]);
                    float2 e1 = __half22float2(*(const __half2*)&s_erj[(r0+8)*136 + c0]);
                    float2 e2 = __half22float2(*(const __half2*)&s_erj[(r0+16)*136 + c0]);
                    float2 e3 = __half22float2(*(const __half2*)&s_erj[(r0+24)*136 + c0]);
                    float h00 = fmaxf(acc0[nt][0] + el.x + e0.x, 0.0f);
                    float h01 = fmaxf(acc0[nt][1] + el.y + e0.y, 0.0f);
                    float h10 = fmaxf(acc0[nt][2] + el.x + e1.x, 0.0f);
                    float h11 = fmaxf(acc0[nt][3] + el.y + e1.y, 0.0f);
                    float h20 = fmaxf(acc1[nt][0] + el.x + e2.x, 0.0f);
                    float h21 = fmaxf(acc1[nt][1] + el.y + e2.y, 0.0f);
                    float h30 = fmaxf(acc1[nt][2] + el.x + e3.x, 0.0f);
                    float h31 = fmaxf(acc1[nt][3] + el.y + e3.y, 0.0f);
                    if (head == 0){
                        const float2 w2 = *(const float2*)&s_w2e[half*128 + c0];
                        eacc[0] = fmaf(h00, w2.x, fmaf(h01, w2.y, eacc[0]));
                        eacc[1] = fmaf(h10, w2.x, fmaf(h11, w2.y, eacc[1]));
                        eacc[2] = fmaf(h20, w2.x, fmaf(h21, w2.y, eacc[2]));
                        eacc[3] = fmaf(h30, w2.x, fmaf(h31, w2.y, eacc[3]));
                    } else {
                        fa[e*2]   = packh2(h00, h01);
                        fa[e*2+1] = packh2(h10, h11);
                        fb[e*2]   = packh2(h20, h21);
                        fb[e*2+1] = packh2(h30, h31);
                    }
                }
                if (head == 1){
                    uint32_t wb0, wb1;
                    ldsm2(wb0, wb1, wbBase + (uint32_t)(chunk*128 + qf*32));
                    mma16816(opA, fa[0],fa[1],fa[2],fa[3], wb0, wb1);
                    mma16816(opB, fb[0],fb[1],fb[2],fb[3], wb0, wb1);
                }
            }
        }

        if (s == 1){
            #pragma unroll
            for (int rh = 0; rh < 4; rh++){
                float v = eacc[rh];
                v += __shfl_xor_sync(0xffffffffu, v, 1);
                v += __shfl_xor_sync(0xffffffffu, v, 2);
                eacc[rh] = v;
            }
            if ((lane & 3) == 0){
                float b2 = eh_b2[0];
                #pragma unroll
                for (int rh = 0; rh < 4; rh++){
                    int jg = j0 + r0 + rh*8;
                    float v = eacc[rh] + b2;
                    if (ig == jg) v = -8.0f;
                    out[EDGE_OFF + b*NN*NN + ig*NN + jg] = v;
                }
            }
        }
    }

    // ---- op output: C layout rows r0,r0+8 (opA), r0+16,r0+24 (opB) ----
    {
        const float bo0 = oh_b2[cq], bo1 = oh_b2[cq + 1];
        #pragma unroll
        for (int mb = 0; mb < 2; mb++){
            const float* oc = mb ? opB : opA;
            #pragma unroll
            for (int rr = 0; rr < 2; rr++){
                int jg = j0 + r0 + mb*16 + rr*8;
                float2* dst = (float2*)&out[OP_OFF
                    + ((size_t)(b*NN*NN + ig*NN + jg))*NOPS + cq];
                *dst = make_float2(oc[rr*2] + bo0, oc[rr*2+1] + bo1);
            }
        }
    }
}

// ---------------------------------------------------------------------------
// Launch
// ---------------------------------------------------------------------------
extern "C" void kernel_launch(void* const* d_in, const int* in_sizes, int n_in,
                              void* d_out, int out_size)
{
    const float* obs    = (const float*)d_in[0];
    const float* latent = (const float*)d_in[1];
    const float* query  = (const float*)d_in[2];
    const float* enc_w1 = (const float*)d_in[3];
    const float* enc_b1 = (const float*)d_in[4];
    const float* enc_w2 = (const float*)d_in[5];
    const float* enc_b2 = (const float*)d_in[6];
    const float* upd_w  = (const float*)d_in[7];
    const float* upd_b  = (const float*)d_in[8];
    const float* gru_wi = (const float*)d_in[9];
    const float* gru_bi = (const float*)d_in[10];
    const float* gru_wh = (const float*)d_in[11];
    const float* gru_bh = (const float*)d_in[12];
    const float* eh_w1  = (const float*)d_in[13];
    const float* eh_b1  = (const float*)d_in[14];
    const float* eh_w2  = (const float*)d_in[15];
    const float* eh_b2  = (const float*)d_in[16];
    const float* oh_w1  = (const float*)d_in[17];
    const float* oh_b1  = (const float*)d_in[18];
    const float* oh_w2  = (const float*)d_in[19];
    const float* oh_b2  = (const float*)d_in[20];
    const float* q_w    = (const float*)d_in[21];
    const float* q_b    = (const float*)d_in[22];
    const float* nh_w1  = (const float*)d_in[23];
    const float* nh_b1  = (const float*)d_in[24];
    const float* nh_w2  = (const float*)d_in[25];
    const float* nh_b2  = (const float*)d_in[26];

    float* out = (float*)d_out;

    static bool inited = false;
    if (!inited){
        cudaFuncSetAttribute(pairKernel, cudaFuncAttributeMaxDynamicSharedMemorySize, PAIR_SMEM);
        inited = true;
    }

    nodeKernel<<<320, 256>>>(obs, latent, query,
                             enc_w1, enc_b1, enc_w2, enc_b2,
                             upd_w, upd_b,
                             gru_wi, gru_bi, gru_wh, gru_bh,
                             q_w, q_b, nh_w1, nh_b1, nh_w2, nh_b2,
                             eh_w1, oh_w1, oh_w2,
                             out + NEXT_OFF);

    elKernel<<<dim3(128, 4), 256>>>(eh_w1, eh_b1, oh_w1, oh_b1);

    pairKernel<<<dim3(8, 32, 4), 256, PAIR_SMEM>>>(eh_w2, eh_b2, oh_b2, out);
}